// round 2
// baseline (speedup 1.0000x reference)
#include <cuda_runtime.h>
#include <cstdint>

#define NQ 50000
#define CDIM 128
#define KNBR 48
#define NHEAD 8
#define HDIM 16
#define FFDIM 256

// ---------------- scratch (device globals; no allocation allowed) ----------------
__device__ float g_QKV[(size_t)NQ * 384];    // [Q | KF | VF] per row
__device__ float g_U[(size_t)NQ * 1024];     // u[n,h,c]
__device__ float g_PBAR[(size_t)NQ * 1024];  // pbar[n,h,c]
__device__ float g_CTX[(size_t)NQ * 128];
__device__ float g_X1[(size_t)NQ * 128];
__device__ float g_H1[(size_t)NQ * 256];
__device__ float g_T1[(size_t)NQ * 128];
__device__ float g_T2[(size_t)NQ * 128];

// ---------------- generic tiled SGEMM: C = A[M,K] @ B[Nc,K]^T + bias ----------------
__global__ __launch_bounds__(256) void sgemm_bias(
    const float* __restrict__ A, const float* __restrict__ B,
    const float* __restrict__ bias, float* __restrict__ C,
    int M, int Nc, int K, int relu)
{
    __shared__ float As[16][64];
    __shared__ float Bs[16][64];
    const int tid = threadIdx.x;
    const int m0 = blockIdx.x * 64, n0 = blockIdx.y * 64;
    const int lr = tid >> 2;            // 0..63
    const int lk = (tid & 3) << 2;      // 0,4,8,12
    const int tx = tid & 15, ty = tid >> 4;
    float acc[4][4] = {};
    for (int k0 = 0; k0 < K; k0 += 16) {
        float4 a4 = make_float4(0.f, 0.f, 0.f, 0.f);
        if (m0 + lr < M)
            a4 = *(const float4*)(A + (size_t)(m0 + lr) * K + k0 + lk);
        float4 b4 = *(const float4*)(B + (size_t)(n0 + lr) * K + k0 + lk);
        if (k0) __syncthreads();
        As[lk + 0][lr] = a4.x; As[lk + 1][lr] = a4.y;
        As[lk + 2][lr] = a4.z; As[lk + 3][lr] = a4.w;
        Bs[lk + 0][lr] = b4.x; Bs[lk + 1][lr] = b4.y;
        Bs[lk + 2][lr] = b4.z; Bs[lk + 3][lr] = b4.w;
        __syncthreads();
#pragma unroll
        for (int kk = 0; kk < 16; kk++) {
            float4 av = *(const float4*)&As[kk][ty << 2];
            float4 bv = *(const float4*)&Bs[kk][tx << 2];
            float a[4] = {av.x, av.y, av.z, av.w};
            float b[4] = {bv.x, bv.y, bv.z, bv.w};
#pragma unroll
            for (int i = 0; i < 4; i++)
#pragma unroll
                for (int j = 0; j < 4; j++) acc[i][j] += a[i] * b[j];
        }
    }
#pragma unroll
    for (int i = 0; i < 4; i++) {
        int r = m0 + (ty << 2) + i;
        if (r >= M) continue;
#pragma unroll
        for (int j = 0; j < 4; j++) {
            int cdx = n0 + (tx << 2) + j;
            float v = acc[i][j] + bias[cdx];
            if (relu) v = fmaxf(v, 0.f);
            C[(size_t)r * Nc + cdx] = v;
        }
    }
}

// ---------------- U: u[n,h,c] = sum_d Q[n,16h+d] * Wk[16h+d, c] ----------------
struct USmem { float Wk[128][132]; float Q[16][128]; };

__global__ __launch_bounds__(256) void u_kernel(const float* __restrict__ ipw)
{
    extern __shared__ char raw0[];
    USmem& sm = *(USmem*)raw0;
    const int tid = threadIdx.x;
    const int n0 = blockIdx.x * 16;
    for (int i = tid; i < 128 * 128; i += 256) {
        int r = i >> 7, c = i & 127;
        sm.Wk[r][c] = ipw[(size_t)(128 + r) * 128 + c];
    }
    for (int i = tid; i < 16 * 128; i += 256) {
        int q = i >> 7, c = i & 127;
        sm.Q[q][c] = g_QKV[(size_t)(n0 + q) * 384 + c];
    }
    __syncthreads();
    const int c = tid & 127;
    const int half = tid >> 7;
    for (int q = 0; q < 16; q++) {
#pragma unroll
        for (int hh = 0; hh < 4; hh++) {
            int h = half * 4 + hh;
            float acc = 0.f;
#pragma unroll
            for (int d = 0; d < 16; d++)
                acc += sm.Q[q][h * 16 + d] * sm.Wk[h * 16 + d][c];
            g_U[(size_t)(n0 + q) * 1024 + h * 128 + c] = acc;
        }
    }
}

// ---------------- fused per-query attention ----------------
struct AttnSmem {
    float KF[48][132];
    float PE[48][132];
    float U[1024];
    float Q[128];
    float S[384];        // scores then attn, [h][k]
    float Rel[48][4];
    int   Idx[48];
    int   Msk[48];
};

__global__ __launch_bounds__(128) void attn_kernel(
    const float* __restrict__ coords,
    const int* __restrict__ kidx,
    const int* __restrict__ kmask,      // int32 (or f32 bits): nonzero => masked
    const float* __restrict__ kposw,
    const float* __restrict__ kposb)
{
    extern __shared__ char raw1[];
    AttnSmem& sm = *(AttnSmem*)raw1;
    const int n = blockIdx.x;
    const int tid = threadIdx.x;   // 128

    const float w0 = kposw[tid * 3 + 0];
    const float w1 = kposw[tid * 3 + 1];
    const float w2 = kposw[tid * 3 + 2];
    const float pb = kposb[tid];

    sm.Q[tid] = g_QKV[(size_t)n * 384 + tid];
#pragma unroll
    for (int i = 0; i < 8; i++)
        sm.U[tid + i * 128] = g_U[(size_t)n * 1024 + tid + i * 128];

    const float qx = coords[n * 3 + 0];
    const float qy = coords[n * 3 + 1];
    const float qz = coords[n * 3 + 2];
    if (tid < 48) {
        int idx = kidx[n * 48 + tid];
        sm.Idx[tid] = idx;
        sm.Msk[tid] = (kmask[n * 48 + tid] != 0) ? 1 : 0;   // dtype-robust
        sm.Rel[tid][0] = coords[idx * 3 + 0] - qx;
        sm.Rel[tid][1] = coords[idx * 3 + 1] - qy;
        sm.Rel[tid][2] = coords[idx * 3 + 2] - qz;
    }
    __syncthreads();

    // gather KF rows + compute pos embedding
#pragma unroll 4
    for (int k = 0; k < 48; k++) {
        sm.KF[k][tid] = __ldg(&g_QKV[(size_t)sm.Idx[k] * 384 + 128 + tid]);
        float pe = fmaxf(w0 * sm.Rel[k][0] + w1 * sm.Rel[k][1] + w2 * sm.Rel[k][2] + pb, 0.f);
        sm.PE[k][tid] = pe;
    }
    __syncthreads();

    // scores: thread handles (h = tid/16, k = tid%16 + {0,16,32})
    {
        const int h = tid >> 4;
        const int kb = tid & 15;
        const float4* u4 = (const float4*)&sm.U[h * 128];
        float s0 = 0.f, s1 = 0.f, s2 = 0.f;
#pragma unroll 8
        for (int c4 = 0; c4 < 32; c4++) {
            float4 uu = u4[c4];
            float4 p0 = *(const float4*)&sm.PE[kb][c4 * 4];
            float4 p1 = *(const float4*)&sm.PE[kb + 16][c4 * 4];
            float4 p2 = *(const float4*)&sm.PE[kb + 32][c4 * 4];
            s0 += uu.x * p0.x + uu.y * p0.y + uu.z * p0.z + uu.w * p0.w;
            s1 += uu.x * p1.x + uu.y * p1.y + uu.z * p1.z + uu.w * p1.w;
            s2 += uu.x * p2.x + uu.y * p2.y + uu.z * p2.z + uu.w * p2.w;
        }
        const float4* q4 = (const float4*)&sm.Q[h * 16];
#pragma unroll
        for (int d4 = 0; d4 < 4; d4++) {
            float4 qq = q4[d4];
            float4 k0v = *(const float4*)&sm.KF[kb][h * 16 + d4 * 4];
            float4 k1v = *(const float4*)&sm.KF[kb + 16][h * 16 + d4 * 4];
            float4 k2v = *(const float4*)&sm.KF[kb + 32][h * 16 + d4 * 4];
            s0 += qq.x * k0v.x + qq.y * k0v.y + qq.z * k0v.z + qq.w * k0v.w;
            s1 += qq.x * k1v.x + qq.y * k1v.y + qq.z * k1v.z + qq.w * k1v.w;
            s2 += qq.x * k2v.x + qq.y * k2v.y + qq.z * k2v.z + qq.w * k2v.w;
        }
        float sv[3] = {s0, s1, s2};
#pragma unroll
        for (int i = 0; i < 3; i++) {
            int k = kb + 16 * i;
            float v = sv[i] * 0.25f;            // 1/sqrt(16)
            if (sm.Msk[k]) v = -1e9f;
            sm.S[h * 48 + k] = v;
        }
    }
    __syncthreads();

    // per-head softmax (8 threads, serial over 48)
    if (tid < 8) {
        float m = -3.4e38f;
        for (int k = 0; k < 48; k++) m = fmaxf(m, sm.S[tid * 48 + k]);
        float sum = 0.f;
        for (int k = 0; k < 48; k++) {
            float e = __expf(sm.S[tid * 48 + k] - m);
            sm.S[tid * 48 + k] = e;
            sum += e;
        }
        float inv = 1.f / sum;
        for (int k = 0; k < 48; k++) sm.S[tid * 48 + k] *= inv;
    }
    __syncthreads();

    // ctx_feat: gather VF rows directly from L2
    {
        const int h = tid >> 4;
        float ctx = 0.f;
#pragma unroll 8
        for (int k = 0; k < 48; k++)
            ctx += sm.S[h * 48 + k] * __ldg(&g_QKV[(size_t)sm.Idx[k] * 384 + 256 + tid]);
        g_CTX[(size_t)n * 128 + tid] = ctx;
    }
    // pbar[h][c] = sum_k attn[h][k] * pe[k][c]
#pragma unroll
    for (int h = 0; h < 8; h++) {
        float pv = 0.f;
#pragma unroll 8
        for (int k = 0; k < 48; k++)
            pv += sm.S[h * 48 + k] * sm.PE[k][tid];
        g_PBAR[(size_t)n * 1024 + h * 128 + tid] = pv;
    }
}

// ---------------- ctx += Wv @ pbar  (per head) ----------------
struct CSmem { float Wv[128][133]; float PB[1024]; };

__global__ __launch_bounds__(128) void ctxpos_kernel(const float* __restrict__ ipw)
{
    extern __shared__ char raw2[];
    CSmem& sm = *(CSmem*)raw2;
    const int tid = threadIdx.x;
    const int n0 = blockIdx.x * 16;
    for (int i = tid; i < 128 * 128; i += 128) {
        int r = i >> 7, c = i & 127;
        sm.Wv[r][c] = ipw[(size_t)(256 + r) * 128 + c];
    }
    for (int q = 0; q < 16; q++) {
        __syncthreads();
#pragma unroll
        for (int i = 0; i < 8; i++)
            sm.PB[tid + i * 128] = g_PBAR[(size_t)(n0 + q) * 1024 + tid + i * 128];
        __syncthreads();
        const int e = tid, h = e >> 4;
        const float* pbr = &sm.PB[h * 128];
        float acc = 0.f;
#pragma unroll 8
        for (int c = 0; c < 128; c++) acc += sm.Wv[e][c] * pbr[c];
        g_CTX[(size_t)(n0 + q) * 128 + e] += acc;
    }
}

// ---------------- layernorm (optional residual, optional relu), C=128 ----------------
__global__ __launch_bounds__(256) void ln_kernel(
    const float* __restrict__ a, const float* __restrict__ b,
    const float* __restrict__ g, const float* __restrict__ bb,
    float* __restrict__ out, int relu)
{
    const int row = blockIdx.x * 8 + (threadIdx.x >> 5);
    const int lane = threadIdx.x & 31;
    if (row >= NQ) return;
    float4 x = ((const float4*)(a + (size_t)row * 128))[lane];
    if (b) {
        float4 y = ((const float4*)(b + (size_t)row * 128))[lane];
        x.x += y.x; x.y += y.y; x.z += y.z; x.w += y.w;
    }
    float s = x.x + x.y + x.z + x.w;
    float s2 = x.x * x.x + x.y * x.y + x.z * x.z + x.w * x.w;
#pragma unroll
    for (int o = 16; o; o >>= 1) {
        s += __shfl_xor_sync(0xffffffffu, s, o);
        s2 += __shfl_xor_sync(0xffffffffu, s2, o);
    }
    const float mean = s * (1.f / 128.f);
    const float var = s2 * (1.f / 128.f) - mean * mean;
    const float rstd = rsqrtf(var + 1e-5f);
    float4 gg = ((const float4*)g)[lane];
    float4 bv = ((const float4*)bb)[lane];
    float4 o4;
    o4.x = (x.x - mean) * rstd * gg.x + bv.x;
    o4.y = (x.y - mean) * rstd * gg.y + bv.y;
    o4.z = (x.z - mean) * rstd * gg.z + bv.z;
    o4.w = (x.w - mean) * rstd * gg.w + bv.w;
    if (relu) {
        o4.x = fmaxf(o4.x, 0.f); o4.y = fmaxf(o4.y, 0.f);
        o4.z = fmaxf(o4.z, 0.f); o4.w = fmaxf(o4.w, 0.f);
    }
    ((float4*)(out + (size_t)row * 128))[lane] = o4;
}

// ---------------- host launcher ----------------
extern "C" void kernel_launch(void* const* d_in, const int* in_sizes, int n_in,
                              void* d_out, int out_size)
{
    const float* vf     = (const float*)d_in[0];
    const float* coords = (const float*)d_in[1];
    const int*   kidx   = (const int*)d_in[2];
    const int*   kmask  = (const int*)d_in[3];   // int32/float32 bits; nonzero = masked
    const float* ipw  = (const float*)d_in[4];
    const float* ipb  = (const float*)d_in[5];
    const float* opw  = (const float*)d_in[6];
    const float* opb  = (const float*)d_in[7];
    const float* kpw  = (const float*)d_in[8];
    const float* kpb  = (const float*)d_in[9];
    const float* ln1g = (const float*)d_in[10];
    const float* ln1b = (const float*)d_in[11];
    const float* ln2g = (const float*)d_in[12];
    const float* ln2b = (const float*)d_in[13];
    const float* ff1w = (const float*)d_in[14];
    const float* ff1b = (const float*)d_in[15];
    const float* ff2w = (const float*)d_in[16];
    const float* ff2b = (const float*)d_in[17];
    const float* outw = (const float*)d_in[18];
    const float* outb = (const float*)d_in[19];
    const float* ln3g = (const float*)d_in[20];
    const float* ln3b = (const float*)d_in[21];
    float* out = (float*)d_out;
    (void)in_sizes; (void)n_in; (void)out_size;

    float *QKV, *U, *PBAR, *CTX, *X1, *H1, *T1, *T2;
    cudaGetSymbolAddress((void**)&QKV,  g_QKV);
    cudaGetSymbolAddress((void**)&U,    g_U);
    cudaGetSymbolAddress((void**)&PBAR, g_PBAR);
    cudaGetSymbolAddress((void**)&CTX,  g_CTX);
    cudaGetSymbolAddress((void**)&X1,   g_X1);
    cudaGetSymbolAddress((void**)&H1,   g_H1);
    cudaGetSymbolAddress((void**)&T1,   g_T1);
    cudaGetSymbolAddress((void**)&T2,   g_T2);

    cudaFuncSetAttribute(u_kernel,      cudaFuncAttributeMaxDynamicSharedMemorySize, (int)sizeof(USmem));
    cudaFuncSetAttribute(attn_kernel,   cudaFuncAttributeMaxDynamicSharedMemorySize, (int)sizeof(AttnSmem));
    cudaFuncSetAttribute(ctxpos_kernel, cudaFuncAttributeMaxDynamicSharedMemorySize, (int)sizeof(CSmem));

    const int MB = (NQ + 63) / 64;   // 782

    // 1. QKV base projections (Q|KF|VF), biases folded
    sgemm_bias<<<dim3(MB, 6), 256>>>(vf, ipw, ipb, QKV, NQ, 384, 128, 0);
    // 2. u[n,h,:] = q_h^T Wk_h
    u_kernel<<<NQ / 16, 256, sizeof(USmem)>>>(ipw);
    // 3. fused attention (scores, softmax, ctx_feat, pbar)
    attn_kernel<<<NQ, 128, sizeof(AttnSmem)>>>(coords, kidx, kmask, kpw, kpb);
    // 4. ctx += Wv_h @ pbar_h
    ctxpos_kernel<<<NQ / 16, 128, sizeof(CSmem)>>>(ipw);
    // 5. attend = ctx @ out_proj^T + b
    sgemm_bias<<<dim3(MB, 2), 256>>>(CTX, opw, opb, T1, NQ, 128, 128, 0);
    // 6. x1 = LN(vf + attend)
    ln_kernel<<<(NQ + 7) / 8, 256>>>(vf, T1, ln1g, ln1b, X1, 0);
    // 7. h = relu(x1 @ ff1^T + b)
    sgemm_bias<<<dim3(MB, 4), 256>>>(X1, ff1w, ff1b, H1, NQ, 256, 128, 1);
    // 8. ff = h @ ff2^T + b
    sgemm_bias<<<dim3(MB, 2), 256>>>(H1, ff2w, ff2b, T1, NQ, 128, 256, 0);
    // 9. x2 = LN(x1 + ff)
    ln_kernel<<<(NQ + 7) / 8, 256>>>(X1, T1, ln2g, ln2b, T2, 0);
    // 10. o = x2 @ out_w^T + b
    sgemm_bias<<<dim3(MB, 2), 256>>>(T2, outw, outb, T1, NQ, 128, 128, 0);
    // 11. out = relu(LN(o))
    ln_kernel<<<(NQ + 7) / 8, 256>>>(T1, nullptr, ln3g, ln3b, out, 1);
}